// round 17
// baseline (speedup 1.0000x reference)
#include <cuda_runtime.h>
#include <cstdint>

#define NN    128
#define BATCH 2
#define LSEQ  2048
#define CL    32
#define PCH   (LSEQ/CL)   // 64 chunks per batch

typedef unsigned long long u64;

// packed f32x2 FMA (sm_103a FFMA2): d.lo += a.lo*b.lo ; d.hi += a.hi*b.hi
__device__ __forceinline__ void ffma2(u64& d, u64 a, u64 b) {
    asm("fma.rn.f32x2 %0, %1, %2, %0;" : "+l"(d) : "l"(a), "l"(b));
}
__device__ __forceinline__ float f2lo(u64 a){ return __int_as_float((int)(unsigned)(a & 0xffffffffull)); }
__device__ __forceinline__ float f2hi(u64 a){ return __int_as_float((int)(unsigned)(a >> 32)); }

// ---------------- device scratch (no allocations allowed) ----------------
// Ad packed: double2 element [m*NN+n] holds Ad[n][4m..4m+3] as 4 floats.
__device__ double2 g_Ad2[32*NN];
__device__ double2 g_M32[32*NN];                  // Ad^32, same layout
__device__ float   g_Bd[NN];
__device__ float   g_lend[BATCH*PCH*NN];          // chunk-end local states
__device__ float   g_carry[BATCH*PCH*NN];

// ---------------- setup: GBT discretization (fp32 forward substitution) --
// P1 = I - 0.5*A is lower triangular (HiPPO-LegS). Block j solves column j
// of P1*Ad = I + 0.5*A (j<128) or P1*Bd = B (j==128). Division-free chain.
__global__ __launch_bounds__(NN) void k_solve(const float* __restrict__ A,
                                              const float* __restrict__ Bv) {
    int j = blockIdx.x, i = threadIdx.x;
    __shared__ float AT_s[NN*(NN+1)/2 + 1];   // packed lower triangle (+1 pad)
    __shared__ float sh[2];

    for (int idx = i; idx < NN*NN; idx += NN) {
        int r = idx >> 7, c = idx & 127;
        if (c <= r) AT_s[r*(r+1)/2 + c] = A[idx];
    }
    __syncthreads();

    int tri_i = i*(i+1)/2;
    float rdiag = 1.f / (1.f - 0.5f * AT_s[tri_i + i]);
    float hrd   = 0.5f * rdiag;

    float rhs;
    if (j < NN) rhs = (i == j ? 1.f : 0.f) + 0.5f * A[i*NN + j];
    else        rhs = Bv[i];
    float y = rhs * rdiag;

    float at = AT_s[tri_i];   // A[i][0]
    #pragma unroll 4
    for (int k = 0; k < NN; k++) {
        float coef = hrd * at;              // off critical path
        if (i == k) sh[k & 1] = y;
        at = AT_s[tri_i + k + 1];           // prefetch next (pad covers k=127)
        __syncthreads();
        float xk = sh[k & 1];
        if (i > k) y = fmaf(coef, xk, y);
    }

    if (j < NN) ((float*)g_Ad2)[(j >> 2)*512 + (i << 2) + (j & 3)] = y;
    else        g_Bd[i] = y;
}

// ---------------- phase A: local scans + Ad^32 columns, 2 units/block ----
// 128 blocks, one co-resident wave (was 256 blocks = 2 waves).
// Blocks [0,64): scan units 2*bid, 2*bid+1 (two adjacent chunks, same
//   batch since the batch boundary index 64 is even).
// Blocks [64,128): power-column units j0=2*(bid-64), j1=j0+1.
// Both units share the same Ad row registers; the two serial chains are
// independent ILP under one barrier per step.
__global__ __launch_bounds__(NN, 1) void k_local32(const float* __restrict__ f) {
    int bid = blockIdx.x;
    int n = threadIdx.x;
    __shared__ float bufA[2][NN], bufB[2][NN];
    __shared__ float fs[2*CL];

    u64 rl[32], rh[32];
    #pragma unroll
    for (int j = 0; j < 32; j++) {
        double2 t = g_Ad2[j*NN + n];
        rl[j] = __double_as_longlong(t.x);
        rh[j] = __double_as_longlong(t.y);
    }

    bool ispow = (bid >= (BATCH*PCH)/2);
    int gid0 = 0, j0 = 0, j1 = 0;
    float bd = 0.f;
    if (!ispow) {
        gid0 = bid*2;                         // unit ids gid0, gid0+1
        int b = gid0 >> 6, p0 = gid0 & 63;
        bd = g_Bd[n];
        if (n < 2*CL) fs[n] = f[b*LSEQ + p0*CL + n];
        bufA[0][n] = 0.f;
        bufB[0][n] = 0.f;
    } else {
        j0 = (bid - (BATCH*PCH)/2)*2; j1 = j0 + 1;
        bufA[0][n] = (n == j0) ? 1.f : 0.f;
        bufB[0][n] = (n == j1) ? 1.f : 0.f;
    }
    __syncthreads();

    int cur = 0;
    float vA = 0.f, vB = 0.f;
    #pragma unroll 1
    for (int i = 0; i < CL; i++) {
        const double2* cA = (const double2*)bufA[cur];
        const double2* cB = (const double2*)bufB[cur];
        u64 aA0 = 0, aA1 = 0, aA2 = 0, aA3 = 0;
        u64 aB0 = 0, aB1 = 0, aB2 = 0, aB3 = 0;
        #pragma unroll
        for (int j = 0; j < 32; j += 2) {
            double2 a0d = cA[j],   a1d = cA[j+1];
            double2 b0d = cB[j],   b1d = cB[j+1];
            ffma2(aA0, rl[j],   __double_as_longlong(a0d.x));
            ffma2(aB0, rl[j],   __double_as_longlong(b0d.x));
            ffma2(aA1, rh[j],   __double_as_longlong(a0d.y));
            ffma2(aB1, rh[j],   __double_as_longlong(b0d.y));
            ffma2(aA2, rl[j+1], __double_as_longlong(a1d.x));
            ffma2(aB2, rl[j+1], __double_as_longlong(b1d.x));
            ffma2(aA3, rh[j+1], __double_as_longlong(a1d.y));
            ffma2(aB3, rh[j+1], __double_as_longlong(b1d.y));
        }
        vA = ((f2lo(aA0)+f2hi(aA0)) + (f2lo(aA1)+f2hi(aA1)))
           + ((f2lo(aA2)+f2hi(aA2)) + (f2lo(aA3)+f2hi(aA3)));
        vB = ((f2lo(aB0)+f2hi(aB0)) + (f2lo(aB1)+f2hi(aB1)))
           + ((f2lo(aB2)+f2hi(aB2)) + (f2lo(aB3)+f2hi(aB3)));
        if (!ispow) {
            vA += bd * fs[i];
            vB += bd * fs[CL + i];
        }
        bufA[cur ^ 1][n] = vA;
        bufB[cur ^ 1][n] = vB;
        cur ^= 1;
        __syncthreads();
    }

    if (!ispow) {
        g_lend[gid0*NN + n]     = vA;
        g_lend[(gid0+1)*NN + n] = vB;
    } else {
        ((float*)g_M32)[(j0 >> 2)*512 + (n << 2) + (j0 & 3)] = vA;
        ((float*)g_M32)[(j1 >> 2)*512 + (n << 2) + (j1 & 3)] = vB;
    }
}

// ---------------- phase B: serial carry chain with Ad^32 -----------------
// carry_0 = 0 ; carry_p = Ad^32 * carry_{p-1} + lend_{p-1}. 128 threads,
// full row in registers, all 63 lend vectors prefetched into shared.
__global__ __launch_bounds__(NN, 1) void k_carry() {
    int b = blockIdx.x;
    int n = threadIdx.x;
    __shared__ double2 cbuf[2][32];
    __shared__ float   lend_s[(PCH-1)*NN];   // 32 KB, coalesced prefetch
    u64 rl[32], rh[32];
    #pragma unroll
    for (int j = 0; j < 32; j++) {
        double2 t = g_M32[j*NN + n];
        rl[j] = __double_as_longlong(t.x);
        rh[j] = __double_as_longlong(t.y);
    }
    for (int idx = n; idx < (PCH-1)*NN; idx += NN)
        lend_s[idx] = g_lend[b*PCH*NN + idx];
    ((float*)cbuf[0])[n] = 0.f;
    g_carry[(b*PCH + 0)*NN + n] = 0.f;
    __syncthreads();

    int cur = 0;
    #pragma unroll 1
    for (int p = 1; p < PCH; p++) {
        u64 a0 = 0, a1 = 0, a2 = 0, a3 = 0;
        #pragma unroll
        for (int j = 0; j < 32; j += 2) {
            double2 c0 = cbuf[cur][j];
            double2 c1 = cbuf[cur][j+1];
            ffma2(a0, rl[j],   __double_as_longlong(c0.x));
            ffma2(a1, rh[j],   __double_as_longlong(c0.y));
            ffma2(a2, rl[j+1], __double_as_longlong(c1.x));
            ffma2(a3, rh[j+1], __double_as_longlong(c1.y));
        }
        float v = ((f2lo(a0)+f2hi(a0)) + (f2lo(a1)+f2hi(a1)))
                + ((f2lo(a2)+f2hi(a2)) + (f2lo(a3)+f2hi(a3)))
                + lend_s[(p-1)*NN + n];
        g_carry[(b*PCH + p)*NN + n] = v;
        ((float*)cbuf[cur ^ 1])[n] = v;
        cur ^= 1;
        __syncthreads();
    }
}

// ---------------- phase C: seeded rescan + broadcast write + c_final -----
// Blocks (b,p,h): re-run chunk recurrence seeded with carry_p and write
// N-row half h of every y[b,t,:,:] tile. Pair-split matvec (n=tid>>1,
// half=tid&1, shfl.xor combine) -> 2 blocks/SM -> one co-resident wave.
// Store-first: stores of state i-1 issue at the TOP of iteration i so the
// 32KB burst drains under this step's matvec (measured -1.5us in R13).
__global__ __launch_bounds__(256, 2) void k_out(float4* __restrict__ out4,
                                                const float* __restrict__ f,
                                                const float* __restrict__ Cv,
                                                const float* __restrict__ Dv,
                                                int yoff4) {
    int idx = blockIdx.x;
    int b = idx >> 7, ph = idx & 127;
    int p = ph >> 1, h = ph & 1;
    int tid = threadIdx.x;
    int n = tid >> 1, half = tid & 1;
    int w = tid >> 5, lane = tid & 31;
    __shared__ float sbufF[2][NN];
    __shared__ float fs[CL];

    u64 rl[16], rh[16];
    #pragma unroll
    for (int jj = 0; jj < 16; jj++) {
        double2 t = g_Ad2[(16*half + jj)*NN + n];
        rl[jj] = __double_as_longlong(t.x);
        rh[jj] = __double_as_longlong(t.y);
    }
    float bd = g_Bd[n];
    if (tid < CL) fs[tid] = f[b*LSEQ + p*CL + tid];
    float creg[8];
    #pragma unroll
    for (int r2 = 0; r2 < 8; r2++) creg[r2] = Cv[h*64 + w*8 + r2];
    float D0 = Dv[0];

    if (!half) sbufF[1][n] = (p > 0) ? __ldcg(&g_carry[(b*PCH + p)*NN + n]) : 0.f;
    __syncthreads();

    float4* yout = out4 + yoff4 + (size_t)(b*LSEQ + p*CL)*NN*(NN/4);

    #pragma unroll 1
    for (int i = 0; i < CL; i++) {
        int cw = i & 1;          // state i written here
        int cr = cw ^ 1;         // state i-1 / seed (stable since last barrier)

        // stores of state i-1 first (drain overlaps this step's matvec)
        if (i > 0) {
            float4 s4 = ((float4*)sbufF[cr])[lane];
            float dfp = D0 * fs[i-1];
            float4* yrow = yout + (size_t)(i-1)*NN*(NN/4) + (h*64 + w*8)*(NN/4) + lane;
            #pragma unroll
            for (int r2 = 0; r2 < 8; r2++) {
                float cn = creg[r2];
                float4 o;
                o.x = fmaf(cn, s4.x, dfp);  o.y = fmaf(cn, s4.y, dfp);
                o.z = fmaf(cn, s4.z, dfp);  o.w = fmaf(cn, s4.w, dfp);
                __stcs(yrow + (size_t)r2*(NN/4), o);
            }
        }

        const double2* c2 = (const double2*)sbufF[cr] + 16*half;
        u64 a0 = 0, a1 = 0, a2 = 0, a3 = 0;
        #pragma unroll
        for (int jj = 0; jj < 16; jj += 2) {
            double2 c0 = c2[jj], c1 = c2[jj+1];
            ffma2(a0, rl[jj],   __double_as_longlong(c0.x));
            ffma2(a1, rh[jj],   __double_as_longlong(c0.y));
            ffma2(a2, rl[jj+1], __double_as_longlong(c1.x));
            ffma2(a3, rh[jj+1], __double_as_longlong(c1.y));
        }
        float part = ((f2lo(a0)+f2hi(a0)) + (f2lo(a1)+f2hi(a1)))
                   + ((f2lo(a2)+f2hi(a2)) + (f2lo(a3)+f2hi(a3)));
        float other = __shfl_xor_sync(0xffffffffu, part, 1);
        float v = part + other + bd * fs[i];
        if (!half) sbufF[cw][n] = v;
        __syncthreads();
    }

    // epilogue: store state CL-1 (in sbufF[(CL-1)&1])
    {
        int cl = (CL-1) & 1;
        float4 s4 = ((float4*)sbufF[cl])[lane];
        float dfp = D0 * fs[CL-1];
        float4* yrow = yout + (size_t)(CL-1)*NN*(NN/4) + (h*64 + w*8)*(NN/4) + lane;
        #pragma unroll
        for (int r2 = 0; r2 < 8; r2++) {
            float cn = creg[r2];
            float4 o;
            o.x = fmaf(cn, s4.x, dfp);  o.y = fmaf(cn, s4.y, dfp);
            o.z = fmaf(cn, s4.z, dfp);  o.w = fmaf(cn, s4.w, dfp);
            __stcs(yrow + (size_t)r2*(NN/4), o);
        }
        // c_final: last chunk, h==0 block writes S[L-1]
        if (p == PCH-1 && h == 0 && yoff4 >= (BATCH*NN/4) && tid < NN/4) {
            out4[b*(NN/4) + tid] = ((float4*)sbufF[cl])[tid];
        }
    }
}

// ---------------- launcher ----------------
extern "C" void kernel_launch(void* const* d_in, const int* in_sizes, int n_in,
                              void* d_out, int out_size) {
    const float* f  = (const float*)d_in[0];  // (BATCH, L, 1)
    const float* A  = (const float*)d_in[1];  // (N, N)
    const float* Bv = (const float*)d_in[2];  // (N, 1)
    const float* Cv = (const float*)d_in[3];  // (N, 1)
    const float* Dv = (const float*)d_in[4];  // (1,)

    k_solve<<<NN + 1, NN>>>(A, Bv);
    k_local32<<<(BATCH*PCH + NN)/2, NN>>>(f);
    k_carry<<<BATCH, NN>>>();

    int ytotal = BATCH * LSEQ * NN * NN;
    int yoff = out_size - ytotal;
    if (yoff < 0) yoff = 0;
    k_out<<<2 * BATCH * PCH, 256>>>((float4*)d_out, f, Cv, Dv, yoff / 4);
}